// round 2
// baseline (speedup 1.0000x reference)
#include <cuda_runtime.h>
#include <cuda_bf16.h>

// CapLayer — exact routing collapse (b0==0, softmax over the caps axis keeps
// coefficients uniform at 1/10 forever):
//   S[b,d]  = 0.1*( sum_{s,k} U[b,s,k]*W[s,d,k] + 144*sum_s Wb[s,d] )
//   U[b,s,k]= sum_{n<144} x[b][s*1152 + n*8 + k]
//   out[b,o,d] = S[b,d] * ||S|| / (1 + ||S||^2)   replicated over o=0..9
//
// Two-kernel plan:
//   A) persistent balanced reduction of x  (memory-bound, 75.5 MB read)
//   B) tiny per-batch GEMV + squash epilogue

#define NUM_SHARED 32
#define IN_DIM 8
#define OUT_DIM 16
#define NUM_OUT 10
#define HW 144
#define X_PER_B (NUM_SHARED * HW * IN_DIM)   // 36864 floats per batch
#define BS 512

#define QUARTERS 4                  // items per batch
#define N_PER_ITEM (HW / QUARTERS)  // 36
#define N_PER_SUB (N_PER_ITEM / 4)  // 9 n-positions per thread sub-group lane
#define ITEMS (BS * QUARTERS)       // 4096
#define GRID_A 592                  // 148 SMs * 4 resident CTAs -> perfect fill
#define THREADS_A 256

// Partial U per item: 64 float4 slots (slot = s*2 + half, components = 4 k's)
__device__ float4 g_Upart[ITEMS * 64];   // 4 MB scratch

__global__ __launch_bounds__(THREADS_A)
void cap_reduce(const float* __restrict__ x)
{
    const int t    = threadIdx.x;
    const int slot = t >> 2;        // 0..63 : s = slot>>1, half = slot&1
    const int qq   = t & 3;         // sub-group lane within the slot
    const int s    = slot >> 1;
    const int half = slot & 1;

    // Base offset independent of item (in floats)
    const int base_sk = s * (HW * IN_DIM) + half * 4;

    for (int item = blockIdx.x; item < ITEMS; item += GRID_A) {
        const int b  = item >> 2;
        const int qn = item & 3;

        const float* p = x + (size_t)b * X_PER_B + base_sk
                         + (qn * N_PER_ITEM + qq * N_PER_SUB) * IN_DIM;

        float4 acc = make_float4(0.f, 0.f, 0.f, 0.f);
        #pragma unroll
        for (int i = 0; i < N_PER_SUB; i++) {
            float4 v = *(const float4*)(p + i * IN_DIM);   // 9 independent LDG.128
            acc.x += v.x; acc.y += v.y; acc.z += v.z; acc.w += v.w;
        }

        // Reduce over the 4 consecutive lanes (qq) with shuffles — no smem/sync.
        #pragma unroll
        for (int m = 1; m < 4; m <<= 1) {
            acc.x += __shfl_xor_sync(0xFFFFFFFFu, acc.x, m);
            acc.y += __shfl_xor_sync(0xFFFFFFFFu, acc.y, m);
            acc.z += __shfl_xor_sync(0xFFFFFFFFu, acc.z, m);
            acc.w += __shfl_xor_sync(0xFFFFFFFFu, acc.w, m);
        }
        if (qq == 0) {
            g_Upart[item * 64 + slot] = acc;
        }
    }
}

__global__ __launch_bounds__(64)
void cap_epilogue(const float* __restrict__ W,
                  const float* __restrict__ Wb,
                  float* __restrict__ out)
{
    __shared__ float U[NUM_SHARED * IN_DIM];   // 256
    __shared__ float Sd[OUT_DIM];
    __shared__ float coeff_sh;

    const int b = blockIdx.x;
    const int t = threadIdx.x;      // 64 threads, one per slot

    // Sum the 4 quarter partials for this batch.
    float4 a0 = g_Upart[(b * 4 + 0) * 64 + t];
    float4 a1 = g_Upart[(b * 4 + 1) * 64 + t];
    float4 a2 = g_Upart[(b * 4 + 2) * 64 + t];
    float4 a3 = g_Upart[(b * 4 + 3) * 64 + t];
    float4 r;
    r.x = (a0.x + a1.x) + (a2.x + a3.x);
    r.y = (a0.y + a1.y) + (a2.y + a3.y);
    r.z = (a0.z + a1.z) + (a2.z + a3.z);
    r.w = (a0.w + a1.w) + (a2.w + a3.w);
    ((float4*)U)[t] = r;            // U[s*8 + half*4 + c] == slot*4 + c
    __syncthreads();

    // GEMV: S[d] = 0.1*( sum_{s,k} U*W + 144*sum_s Wb )
    if (t < OUT_DIM) {
        const int d = t;
        float acc0 = 0.f, acc1 = 0.f;
        #pragma unroll
        for (int s2 = 0; s2 < NUM_SHARED; s2 += 2) {
            acc0 += 144.f * Wb[s2 * OUT_DIM + d];
            acc1 += 144.f * Wb[(s2 + 1) * OUT_DIM + d];
            #pragma unroll
            for (int k2 = 0; k2 < IN_DIM; k2++) {
                acc0 += U[s2 * IN_DIM + k2]       * W[(s2 * OUT_DIM + d) * IN_DIM + k2];
                acc1 += U[(s2 + 1) * IN_DIM + k2] * W[((s2 + 1) * OUT_DIM + d) * IN_DIM + k2];
            }
        }
        Sd[d] = 0.1f * (acc0 + acc1);
    }
    __syncthreads();

    if (t == 0) {
        float n2 = 0.f;
        #pragma unroll
        for (int d = 0; d < OUT_DIM; d++) n2 += Sd[d] * Sd[d];
        coeff_sh = sqrtf(n2) / (1.f + n2);
    }
    __syncthreads();

    // out[b][o][d] = Sd[d] * coeff, 160 values with 64 threads
    const float c = coeff_sh;
    float* ob = out + (size_t)b * (NUM_OUT * OUT_DIM);
    #pragma unroll
    for (int i = t; i < NUM_OUT * OUT_DIM; i += 64) {
        ob[i] = Sd[i & (OUT_DIM - 1)] * c;
    }
}

extern "C" void kernel_launch(void* const* d_in, const int* in_sizes, int n_in,
                              void* d_out, int out_size)
{
    const float* x  = (const float*)d_in[0];
    const float* W  = (const float*)d_in[1];
    const float* Wb = (const float*)d_in[2];
    // d_in[3] = b0 (zeros) — unused after the routing collapse.
    float* out = (float*)d_out;

    cap_reduce<<<GRID_A, THREADS_A>>>(x);
    cap_epilogue<<<BS, 64>>>(W, Wb, out);
}

// round 3
// speedup vs baseline: 1.5442x; 1.5442x over previous
#include <cuda_runtime.h>
#include <cuda_bf16.h>

// CapLayer — exact routing collapse (b0==0; softmax over the caps axis keeps
// coefficients uniform at 1/10 in every routing iteration):
//   U[b,s,k] = sum_{n<144} x[b][s*1152 + n*8 + k]
//   S[b,d]   = 0.1*( sum_{s,k} U[b,s,k]*W[s,d,k] + 144*sum_s Wb[s,d] )
//   out[b,o,d] = S[b,d] * ||S|| / (1 + ||S||^2)   replicated over o=0..9
//
// Single fused kernel. x fits in L2 (75.5MB < 126MB) and stays resident across
// graph replays, so the binder is L2 bandwidth -> maximize coalescing + MLP.
//
// Load mapping: per batch, x is 9216 float4. Group s owns float4 indices
// [s*288, (s+1)*288) ; 288 = 9 warp-chunks of 32. Warp w handles s = w*8..w*8+7.
// For chunk c, lane l loads f = s*288 + c*32 + l  (contiguous 512B per warp
// instruction, 4 fully-consumed 128B lines). Lane parity = k-half (f&1), so
// summing over chunks accumulates over n only. Parity-preserving shfl_xor
// (masks 2,4,8,16) finishes the n-reduction; lanes 0/1 hold U[s][0:4]/U[s][4:8].

#define NUM_SHARED 32
#define IN_DIM 8
#define OUT_DIM 16
#define NUM_OUT 10
#define HW 144
#define X_PER_B (NUM_SHARED * HW * IN_DIM)   // 36864 floats
#define BS 512

__global__ __launch_bounds__(128, 4)
void caplayer_kernel(const float* __restrict__ x,
                     const float* __restrict__ W,
                     const float* __restrict__ Wb,
                     float* __restrict__ out)
{
    __shared__ float U[NUM_SHARED * IN_DIM];   // 256 floats
    __shared__ float Sd[OUT_DIM];
    __shared__ float coeff_sh;

    const int b    = blockIdx.x;
    const int t    = threadIdx.x;
    const int w    = t >> 5;        // warp 0..3 -> s = w*8 .. w*8+7
    const int lane = t & 31;

    const float4* xb = (const float4*)(x + (size_t)b * X_PER_B);

    // ---- Phase 1: 72 independent fully-coalesced LDG.128 per thread
    float4 acc[8];
    #pragma unroll
    for (int si = 0; si < 8; si++)
        acc[si] = make_float4(0.f, 0.f, 0.f, 0.f);

    const int base = (w * 8) * 288 + lane;
    #pragma unroll
    for (int si = 0; si < 8; si++) {
        #pragma unroll
        for (int c = 0; c < 9; c++) {
            float4 v = xb[base + si * 288 + c * 32];
            acc[si].x += v.x; acc[si].y += v.y;
            acc[si].z += v.z; acc[si].w += v.w;
        }
    }

    // ---- Phase 2: parity-preserving warp reduction (sum over n)
    #pragma unroll
    for (int si = 0; si < 8; si++) {
        #pragma unroll
        for (int m = 2; m < 32; m <<= 1) {
            acc[si].x += __shfl_xor_sync(0xFFFFFFFFu, acc[si].x, m);
            acc[si].y += __shfl_xor_sync(0xFFFFFFFFu, acc[si].y, m);
            acc[si].z += __shfl_xor_sync(0xFFFFFFFFu, acc[si].z, m);
            acc[si].w += __shfl_xor_sync(0xFFFFFFFFu, acc[si].w, m);
        }
        if (lane < 2) {
            // lane 0 -> U[s][0:4], lane 1 -> U[s][4:8]
            *(float4*)&U[(w * 8 + si) * IN_DIM + lane * 4] = acc[si];
        }
    }
    __syncthreads();

    // ---- Phase 3: tiny GEMV  S[d] = 0.1*( sum_{s,k} U*W + 144*sum_s Wb )
    if (t < OUT_DIM) {
        const int d = t;
        float acc0 = 0.f, acc1 = 0.f;
        #pragma unroll
        for (int s2 = 0; s2 < NUM_SHARED; s2 += 2) {
            acc0 += 144.f * Wb[s2 * OUT_DIM + d];
            acc1 += 144.f * Wb[(s2 + 1) * OUT_DIM + d];
            #pragma unroll
            for (int k2 = 0; k2 < IN_DIM; k2++) {
                acc0 += U[s2 * IN_DIM + k2]       * W[(s2 * OUT_DIM + d) * IN_DIM + k2];
                acc1 += U[(s2 + 1) * IN_DIM + k2] * W[((s2 + 1) * OUT_DIM + d) * IN_DIM + k2];
            }
        }
        Sd[d] = 0.1f * (acc0 + acc1);
    }
    __syncthreads();

    // ---- Phase 4: squash coefficient
    if (t == 0) {
        float n2 = 0.f;
        #pragma unroll
        for (int d = 0; d < OUT_DIM; d++) n2 += Sd[d] * Sd[d];
        coeff_sh = sqrtf(n2) / (1.f + n2);
    }
    __syncthreads();

    // ---- Phase 5: write v replicated over the 10 caps (160 floats)
    const float c = coeff_sh;
    float* ob = out + (size_t)b * (NUM_OUT * OUT_DIM);
    #pragma unroll
    for (int i = t; i < NUM_OUT * OUT_DIM; i += 128) {
        ob[i] = Sd[i & (OUT_DIM - 1)] * c;
    }
}

extern "C" void kernel_launch(void* const* d_in, const int* in_sizes, int n_in,
                              void* d_out, int out_size)
{
    const float* x  = (const float*)d_in[0];
    const float* W  = (const float*)d_in[1];
    const float* Wb = (const float*)d_in[2];
    // d_in[3] = b0 (zeros) — unused after the routing collapse.
    float* out = (float*)d_out;

    caplayer_kernel<<<BS, 128>>>(x, W, Wb, out);
}